// round 1
// baseline (speedup 1.0000x reference)
#include <cuda_runtime.h>
#include <math.h>

#define N 8192
#define D 64
#define LRELU_ALPHA 0.2f

// ---------------- scratch (device globals; no allocation allowed) -----------
__device__ float  g_h[N * D];        // projected features   (2 MB)
__device__ float  g_f1[N];
__device__ float  g_f2[N];
__device__ float  g_f2s[N];          // f2 sorted ascending
__device__ int    g_sidx[N];         // sorted order -> original index
__device__ double g_Phi[N * D];      // inclusive prefix of e^{f2} h   layout [k][d] (4 MB)
__device__ double g_Plo[N * D];      // inclusive prefix of e^{a f2} h layout [k][d] (4 MB)
__device__ double g_pshi[N];         // scalar prefix of e^{f2}
__device__ double g_pslo[N];         // scalar prefix of e^{a f2}

// ---------------- kernel 1: h = x*Wt, f1 = h.a1 + b1, f2 = h.a2 + b2 --------
__global__ void k_proj(const float* __restrict__ x, const float* __restrict__ Wt,
                       const float* __restrict__ a1, const float* __restrict__ b1,
                       const float* __restrict__ a2, const float* __restrict__ b2) {
    __shared__ float Wts[D * D];
    __shared__ float a1s[D], a2s[D];
    __shared__ float xs[8 * D];
    __shared__ float red1[16], red2[16];

    int tid = threadIdx.x;                 // 512 threads
    for (int i = tid; i < D * D; i += 512) Wts[i] = Wt[i];
    if (tid < D) { a1s[tid] = a1[tid]; a2s[tid] = a2[tid]; }
    int row0 = blockIdx.x * 8;
    for (int i = tid; i < 8 * D; i += 512) xs[i] = x[row0 * D + i];
    __syncthreads();

    int r = tid >> 6;                      // 0..7 local row
    int d = tid & 63;
    float h = 0.f;
    #pragma unroll
    for (int k = 0; k < D; k++) h = fmaf(xs[r * D + k], Wts[k * D + d], h);
    g_h[(row0 + r) * D + d] = h;

    float p1 = h * a1s[d];
    float p2 = h * a2s[d];
    #pragma unroll
    for (int off = 16; off > 0; off >>= 1) {
        p1 += __shfl_down_sync(0xffffffffu, p1, off);
        p2 += __shfl_down_sync(0xffffffffu, p2, off);
    }
    int warp = tid >> 5;
    if ((tid & 31) == 0) { red1[warp] = p1; red2[warp] = p2; }
    __syncthreads();
    if (tid < 8) {
        g_f1[row0 + tid] = red1[2 * tid] + red1[2 * tid + 1] + b1[0];
        g_f2[row0 + tid] = red2[2 * tid] + red2[2 * tid + 1] + b2[0];
    }
}

// ---------------- kernel 2: ranking sort of f2 (deterministic permutation) --
// key = order-preserving flipped float; ties broken by index -> exact permutation.
__global__ void __launch_bounds__(1024) k_rank() {
    __shared__ unsigned int kf[N];         // 32 KB
    int t = threadIdx.x;                   // 1024 threads
    for (int i = t; i < N; i += 1024) {
        unsigned int u = __float_as_uint(g_f2[i]);
        kf[i] = u ^ ((u >> 31) ? 0xFFFFFFFFu : 0x80000000u);
    }
    __syncthreads();

    int local_i = t >> 4;                  // 0..63, 16 threads per i (within half-warp)
    int seg     = t & 15;
    int i = blockIdx.x * 64 + local_i;     // 128 blocks * 64 = 8192
    unsigned int ui = kf[i];

    int rank = 0;
    const uint4* kf4 = (const uint4*)kf;
    int j0 = seg * 512;
    #pragma unroll 4
    for (int q = 0; q < 128; q++) {
        uint4 w = kf4[(j0 >> 2) + q];
        int jb = j0 + q * 4;
        rank += (w.x < ui) + (w.y < ui) + (w.z < ui) + (w.w < ui);
        if (w.x == ui) rank += (jb + 0 < i);
        if (w.y == ui) rank += (jb + 1 < i);
        if (w.z == ui) rank += (jb + 2 < i);
        if (w.w == ui) rank += (jb + 3 < i);
    }
    #pragma unroll
    for (int off = 8; off > 0; off >>= 1)
        rank += __shfl_down_sync(0xffffffffu, rank, off, 16);
    if (seg == 0) {
        g_f2s[rank]  = g_f2[i];
        g_sidx[rank] = i;
    }
}

// ---------------- kernel 3: 130 inclusive scans over sorted order -----------
// block b: b<64   -> dim b of e^{f2} * h       -> g_Phi
//          b<128  -> dim b-64 of e^{a f2} * h  -> g_Plo
//          b==128 -> scalar e^{f2}             -> g_pshi
//          b==129 -> scalar e^{a f2}           -> g_pslo
__global__ void __launch_bounds__(1024) k_scan() {
    __shared__ double s[1024];
    int t = threadIdx.x;
    int b = blockIdx.x;
    bool scalar = (b >= 128);
    bool isHi   = scalar ? (b == 128) : (b < 64);
    int  dim    = scalar ? 0 : (isHi ? b : b - 64);
    float scale = isHi ? 1.0f : LRELU_ALPHA;

    double v[8];
    double run = 0.0;
    int k0 = t * 8;
    #pragma unroll
    for (int j = 0; j < 8; j++) {
        int k = k0 + j;
        float e = expf(scale * g_f2s[k]);
        double val;
        if (scalar) val = (double)e;
        else        val = (double)e * (double)g_h[g_sidx[k] * D + dim];
        run += val;
        v[j] = run;
    }
    s[t] = run;
    __syncthreads();
    #pragma unroll
    for (int off = 1; off < 1024; off <<= 1) {
        double add = (t >= off) ? s[t - off] : 0.0;
        __syncthreads();
        s[t] += add;
        __syncthreads();
    }
    double excl = (t > 0) ? s[t - 1] : 0.0;

    if (scalar) {
        double* out = isHi ? g_pshi : g_pslo;
        #pragma unroll
        for (int j = 0; j < 8; j++) out[k0 + j] = excl + v[j];
    } else {
        double* out = isHi ? g_Phi : g_Plo;
        #pragma unroll
        for (int j = 0; j < 8; j++) out[(k0 + j) * D + dim] = excl + v[j];
    }
}

// ---------------- kernel 4: per-row combine + ELU ---------------------------
__global__ void k_out(float* __restrict__ out) {
    __shared__ int    sp[4];
    __shared__ double sc[4];
    int t = threadIdx.x;                   // 256 threads, 4 rows
    int r = t >> 6, d = t & 63;
    int row = blockIdx.x * 4 + r;

    if (d == 0) {
        float f1 = g_f1[row];
        float tt = -f1;
        int lo = 0, hi = N;                // p = #{ f2s <= tt }
        while (lo < hi) {
            int mid = (lo + hi) >> 1;
            if (g_f2s[mid] <= tt) lo = mid + 1; else hi = mid;
        }
        sp[r] = lo;
        sc[r] = exp((double)(LRELU_ALPHA - 1.0f) * (double)f1);   // e^{-0.8 f1}
    }
    __syncthreads();
    int p = sp[r];
    double c = sc[r];

    double tot_hi = g_Phi[(N - 1) * D + d];
    double ph = 0.0, pl = 0.0, psh = 0.0, psl = 0.0;
    if (p > 0) {
        ph  = g_Phi[(p - 1) * D + d];
        pl  = g_Plo[(p - 1) * D + d];
        psh = g_pshi[p - 1];
        psl = g_pslo[p - 1];
    }
    double tsh = g_pshi[N - 1];

    double num = (tot_hi - ph) + c * pl;
    double den = (tsh - psh) + c * psl;
    double v = num / den;
    double o = (v > 0.0) ? v : expm1(v);   // ELU (alpha=1)
    out[row * D + d] = (float)o;
}

// ---------------- launch ----------------------------------------------------
extern "C" void kernel_launch(void* const* d_in, const int* in_sizes, int n_in,
                              void* d_out, int out_size) {
    const float* x  = (const float*)d_in[0];
    const float* Wt = (const float*)d_in[1];
    const float* a1 = (const float*)d_in[2];
    const float* b1 = (const float*)d_in[3];
    const float* a2 = (const float*)d_in[4];
    const float* b2 = (const float*)d_in[5];
    float* out = (float*)d_out;

    k_proj<<<N / 8, 512>>>(x, Wt, a1, b1, a2, b2);
    k_rank<<<N / 64, 1024>>>();
    k_scan<<<130, 1024>>>();
    k_out<<<N / 4, 256>>>(out);
}

// round 3
// speedup vs baseline: 1.8031x; 1.8031x over previous
#include <cuda_runtime.h>
#include <math.h>

#define N 8192
#define D 64
#define ALPHA 0.2f
#define NB 16384
#define SHIFT 18   // bucket = top 14 bits of order-flipped float key

// ---------------- scratch (device globals) ----------------------------------
__device__ float    g_h[N * D];        // projected features (2 MB)
__device__ float    g_hs[N * D];       // h in sorted-f2 order (2 MB)
__device__ float    g_f1[N];
__device__ float    g_f2[N];
__device__ unsigned g_ukey[N];         // order-preserving uint key of f2
__device__ int      g_hist[NB];
__device__ int      g_start[NB];
__device__ int      g_cursor[NB];
__device__ unsigned g_bkey[N];         // bucket-grouped keys
__device__ int      g_bidx[N];         // bucket-grouped original indices
__device__ float    g_f2s[N];          // f2 sorted ascending
__device__ int      g_sidx[N];
__device__ float    g_ehi[N];          // e^{f2s}
__device__ float    g_elo[N];          // e^{ALPHA*f2s}
__device__ double   g_Phi[N * D];      // inclusive prefix of e^{f2} h, [k][d]
__device__ double   g_Plo[N * D];      // inclusive prefix of e^{a f2} h, [k][d]
__device__ double   g_pshi[N];
__device__ double   g_pslo[N];

// ---------------- kernel: zero histogram ------------------------------------
__global__ void k_zero() {
    g_hist[blockIdx.x * 1024 + threadIdx.x] = 0;
}

// ---------------- kernel: projection + scores + key/histogram ---------------
__global__ void k_proj(const float* __restrict__ x, const float* __restrict__ Wt,
                       const float* __restrict__ a1, const float* __restrict__ b1,
                       const float* __restrict__ a2, const float* __restrict__ b2) {
    __shared__ float Wts[D * D];
    __shared__ float a1s[D], a2s[D];
    __shared__ float xs[8 * D];
    __shared__ float red1[16], red2[16];

    int tid = threadIdx.x;                 // 512 threads
    for (int i = tid; i < D * D; i += 512) Wts[i] = Wt[i];
    if (tid < D) { a1s[tid] = a1[tid]; a2s[tid] = a2[tid]; }
    int row0 = blockIdx.x * 8;
    for (int i = tid; i < 8 * D; i += 512) xs[i] = x[row0 * D + i];
    __syncthreads();

    int r = tid >> 6;
    int d = tid & 63;
    float h = 0.f;
    #pragma unroll
    for (int k = 0; k < D; k++) h = fmaf(xs[r * D + k], Wts[k * D + d], h);
    g_h[(row0 + r) * D + d] = h;

    float p1 = h * a1s[d];
    float p2 = h * a2s[d];
    #pragma unroll
    for (int off = 16; off > 0; off >>= 1) {
        p1 += __shfl_down_sync(0xffffffffu, p1, off);
        p2 += __shfl_down_sync(0xffffffffu, p2, off);
    }
    int warp = tid >> 5;
    if ((tid & 31) == 0) { red1[warp] = p1; red2[warp] = p2; }
    __syncthreads();
    if (tid < 8) {
        float f1 = red1[2 * tid] + red1[2 * tid + 1] + b1[0];
        float f2 = red2[2 * tid] + red2[2 * tid + 1] + b2[0];
        g_f1[row0 + tid] = f1;
        g_f2[row0 + tid] = f2;
        unsigned u = __float_as_uint(f2);
        u ^= (u >> 31) ? 0xFFFFFFFFu : 0x80000000u;
        g_ukey[row0 + tid] = u;
        atomicAdd(&g_hist[u >> SHIFT], 1);
    }
}

// ---------------- kernel: exclusive scan of histogram (1 block) -------------
__global__ void __launch_bounds__(1024) k_hscan() {
    __shared__ int warptot[32];
    int t = threadIdx.x;
    int base = t * 16;
    int loc[16];
    int sum = 0;
    #pragma unroll
    for (int j = 0; j < 16; j++) { loc[j] = sum; sum += g_hist[base + j]; }

    int lane = t & 31, warp = t >> 5;
    int w = sum;
    #pragma unroll
    for (int off = 1; off < 32; off <<= 1) {
        int o = __shfl_up_sync(0xffffffffu, w, off);
        if (lane >= off) w += o;
    }
    if (lane == 31) warptot[warp] = w;
    __syncthreads();
    if (t < 32) {
        int v = warptot[t];
        #pragma unroll
        for (int off = 1; off < 32; off <<= 1) {
            int o = __shfl_up_sync(0xffffffffu, v, off);
            if (t >= off) v += o;
        }
        warptot[t] = v;
    }
    __syncthreads();
    int excl = (w - sum) + (warp ? warptot[warp - 1] : 0);
    #pragma unroll
    for (int j = 0; j < 16; j++) {
        int s = excl + loc[j];
        g_start[base + j]  = s;
        g_cursor[base + j] = s;
    }
}

// ---------------- kernel: scatter into buckets ------------------------------
__global__ void k_scatter() {
    int i = blockIdx.x * 1024 + threadIdx.x;
    unsigned u = g_ukey[i];
    int b = u >> SHIFT;
    int pos = atomicAdd(&g_cursor[b], 1);
    g_bkey[pos] = u;
    g_bidx[pos] = i;
}

// ---------------- kernel: rank within bucket + emit sorted arrays -----------
__global__ void k_rankfin() {
    int s = blockIdx.x * 1024 + threadIdx.x;
    unsigned u = g_bkey[s];
    int i = g_bidx[s];
    int b = u >> SHIFT;
    int st = g_start[b];
    int en = st + g_hist[b];
    int rank = st;
    for (int j = st; j < en; j++) {
        unsigned kj = g_bkey[j];
        int ij = g_bidx[j];
        rank += (kj < u) || (kj == u && ij < i);
    }
    float f2v = g_f2[i];
    g_f2s[rank]  = f2v;
    g_sidx[rank] = i;
    g_ehi[rank]  = expf(f2v);
    g_elo[rank]  = expf(ALPHA * f2v);
}

// ---------------- kernel: reorder h into sorted order -----------------------
__global__ void k_reorder() {
    int t = threadIdx.x;                   // 512 threads, 8 rows
    int k = blockIdx.x * 8 + (t >> 6);
    int d = t & 63;
    g_hs[k * D + d] = g_h[g_sidx[k] * D + d];
}

// ---------------- kernel: 130 inclusive scans (warp-shuffle) ----------------
__global__ void __launch_bounds__(1024) k_scan() {
    __shared__ double warptot[32];
    int t = threadIdx.x;
    int b = blockIdx.x;
    bool scalar = (b >= 128);
    bool hi = scalar ? (b == 128) : (b < 64);
    int dim = scalar ? 0 : (hi ? b : b - 64);
    const float* e = hi ? g_ehi : g_elo;

    int k0 = t * 8;
    double v[8];
    double run = 0.0;
    #pragma unroll
    for (int j = 0; j < 8; j++) {
        int k = k0 + j;
        double val = (double)e[k];
        if (!scalar) val *= (double)g_hs[k * D + dim];
        run += val;
        v[j] = run;
    }
    int lane = t & 31, warp = t >> 5;
    double w = run;
    #pragma unroll
    for (int off = 1; off < 32; off <<= 1) {
        double o = __shfl_up_sync(0xffffffffu, w, off);
        if (lane >= off) w += o;
    }
    if (lane == 31) warptot[warp] = w;
    __syncthreads();
    if (t < 32) {
        double x2 = warptot[t];
        #pragma unroll
        for (int off = 1; off < 32; off <<= 1) {
            double o = __shfl_up_sync(0xffffffffu, x2, off);
            if (t >= off) x2 += o;
        }
        warptot[t] = x2;
    }
    __syncthreads();
    double base = (w - run) + (warp ? warptot[warp - 1] : 0.0);

    if (scalar) {
        double* out = hi ? g_pshi : g_pslo;
        #pragma unroll
        for (int j = 0; j < 8; j++) out[k0 + j] = base + v[j];
    } else {
        double* out = hi ? g_Phi : g_Plo;
        #pragma unroll
        for (int j = 0; j < 8; j++) out[(k0 + j) * D + dim] = base + v[j];
    }
}

// ---------------- kernel: per-row combine + ELU -----------------------------
__global__ void k_out(float* __restrict__ out) {
    int t = threadIdx.x;                   // 256 threads, 4 rows
    int row = blockIdx.x * 4 + (t >> 6);
    int d = t & 63;

    float f1 = g_f1[row];
    float tt = -f1;
    int lo = 0, hi2 = N;                   // p = #{ f2s <= -f1 } (redundant per thread)
    while (lo < hi2) {
        int mid = (lo + hi2) >> 1;
        if (g_f2s[mid] <= tt) lo = mid + 1; else hi2 = mid;
    }
    int p = lo;
    float c = expf((ALPHA - 1.0f) * f1);   // e^{-0.8 f1}

    double tot_hi = g_Phi[(N - 1) * D + d];
    double tsh    = g_pshi[N - 1];
    double ph = 0.0, pl = 0.0, psh = 0.0, psl = 0.0;
    if (p > 0) {
        ph  = g_Phi[(p - 1) * D + d];
        pl  = g_Plo[(p - 1) * D + d];
        psh = g_pshi[p - 1];
        psl = g_pslo[p - 1];
    }
    double num = (tot_hi - ph) + (double)c * pl;
    double den = (tsh - psh) + (double)c * psl;
    float v = (float)num / (float)den;
    out[row * D + d] = (v > 0.0f) ? v : expm1f(v);
}

// ---------------- launch ----------------------------------------------------
extern "C" void kernel_launch(void* const* d_in, const int* in_sizes, int n_in,
                              void* d_out, int out_size) {
    const float* x  = (const float*)d_in[0];
    const float* Wt = (const float*)d_in[1];
    const float* a1 = (const float*)d_in[2];
    const float* b1 = (const float*)d_in[3];
    const float* a2 = (const float*)d_in[4];
    const float* b2 = (const float*)d_in[5];
    float* out = (float*)d_out;

    k_zero<<<NB / 1024, 1024>>>();
    k_proj<<<N / 8, 512>>>(x, Wt, a1, b1, a2, b2);
    k_hscan<<<1, 1024>>>();
    k_scatter<<<N / 1024, 1024>>>();
    k_rankfin<<<N / 1024, 1024>>>();
    k_reorder<<<N / 8, 512>>>();
    k_scan<<<130, 1024>>>();
    k_out<<<N / 4, 256>>>(out);
}